// round 1
// baseline (speedup 1.0000x reference)
#include <cuda_runtime.h>
#include <cuda_bf16.h>
#include <math.h>

// Problem constants (fixed by the dataset)
#define TT 1024
#define SS 512
#define DD 32
#define KK 64
#define LOG2PI 1.8378770664093453f

// Precomputed per-state parameters (device globals: no allocations allowed)
__device__ float g_ninv[KK * DD];   // -0.5 / covar
__device__ float g_miv [KK * DD];   // mean / covar
__device__ float g_base[KK];        // -0.5*(sum m^2/c + sum log c + D*log(2pi))
__device__ float g_logden[SS];      // per-sequence sum of log(denominator)

// ---------------------------------------------------------------------------
// Precompute kernel: one thread per state k
// ---------------------------------------------------------------------------
__global__ void precompute_kernel(const float* __restrict__ means,
                                  const float* __restrict__ covars) {
    int k = threadIdx.x;
    if (k >= KK) return;
    float sum_m2ic = 0.0f;
    float sum_logc = 0.0f;
    #pragma unroll
    for (int d = 0; d < DD; d++) {
        float c = covars[k * DD + d];
        float m = means [k * DD + d];
        float ic = 1.0f / c;
        g_ninv[k * DD + d] = -0.5f * ic;
        g_miv [k * DD + d] = m * ic;
        sum_m2ic += m * m * ic;
        sum_logc += logf(c);
    }
    g_base[k] = -0.5f * (sum_m2ic + sum_logc + (float)DD * LOG2PI);
}

// ---------------------------------------------------------------------------
// Forward kernel: one block per sequence s, one thread per state k.
// Per step: emission (reg-resident params), transition (reg-resident A column,
// shared-broadcast alpha), block reduce, normalize. x_t prefetched 2 steps
// ahead via a register + 2-buffer shared ring to hide DRAM latency.
// ---------------------------------------------------------------------------
__global__ __launch_bounds__(KK) void hmm_forward_kernel(
    const float* __restrict__ data,      // [T, S, D]
    const float* __restrict__ initp,     // [K]
    const float* __restrict__ A,         // [K, K] row-stochastic
    float* __restrict__ out)             // [S, K] alpha
{
    const int s = blockIdx.x;
    const int k = threadIdx.x;

    __shared__ __align__(16) float A_sh[KK * KK];
    __shared__ __align__(16) float xsh[2][DD];
    __shared__ __align__(16) float alpha_sh[KK];
    __shared__ float red_sh[2];

    // Cooperative coalesced load of A into shared
    for (int i = k; i < KK * KK; i += KK) A_sh[i] = A[i];

    // Per-state parameters into registers (float4 loads, conflict-free)
    float ninv[DD], miv[DD];
    {
        const float4* n4 = reinterpret_cast<const float4*>(&g_ninv[k * DD]);
        const float4* m4 = reinterpret_cast<const float4*>(&g_miv [k * DD]);
        #pragma unroll
        for (int i = 0; i < DD / 4; i++) {
            float4 a = n4[i];
            ninv[4*i+0] = a.x; ninv[4*i+1] = a.y; ninv[4*i+2] = a.z; ninv[4*i+3] = a.w;
            float4 b = m4[i];
            miv [4*i+0] = b.x; miv [4*i+1] = b.y; miv [4*i+2] = b.z; miv [4*i+3] = b.w;
        }
    }
    const float base  = g_base[k];
    const float initk = initp[k];

    __syncthreads();

    // A column for state k into registers: A[j][k], j = 0..63.
    // Per unrolled j, lanes read consecutive addresses -> conflict-free.
    float Acol[KK];
    #pragma unroll
    for (int j = 0; j < KK; j++) Acol[j] = A_sh[j * KK + k];

    // Prologue: x(0) into shared, x(1) into register
    const float* dptr = data + (size_t)s * DD;   // data[t,s,d] = data[(t*S+s)*D + d]
    float xnext = 0.0f;
    if (k < DD) {
        xsh[0][k] = __ldg(dptr + k);
        xnext     = __ldg(dptr + (size_t)1 * SS * DD + k);
    }
    float logden = 0.0f;
    float an = 0.0f;
    __syncthreads();

    for (int t = 0; t < TT; t++) {
        // Stage next x; issue load for t+2 (2-deep latency hiding)
        if (k < DD) {
            xsh[(t + 1) & 1][k] = xnext;
            if (t + 2 < TT)
                xnext = __ldg(dptr + (size_t)(t + 2) * SS * DD + k);
        }

        // Emission: logp = base + sum_d x*(ninv*x + miv)
        float logp = base;
        const float4* xr4 = reinterpret_cast<const float4*>(xsh[t & 1]);
        #pragma unroll
        for (int dd = 0; dd < DD / 4; dd++) {
            float4 x4 = xr4[dd];
            logp = fmaf(x4.x, fmaf(ninv[4*dd+0], x4.x, miv[4*dd+0]), logp);
            logp = fmaf(x4.y, fmaf(ninv[4*dd+1], x4.y, miv[4*dd+1]), logp);
            logp = fmaf(x4.z, fmaf(ninv[4*dd+2], x4.z, miv[4*dd+2]), logp);
            logp = fmaf(x4.w, fmaf(ninv[4*dd+3], x4.w, miv[4*dd+3]), logp);
        }
        float p = __expf(logp);

        // Transition: acc = p * sum_j alpha[j] * A[j][k]
        float acc;
        if (t == 0) {
            acc = initk * p;
        } else {
            float sum = 0.0f;
            const float4* a4 = reinterpret_cast<const float4*>(alpha_sh);
            #pragma unroll
            for (int jj = 0; jj < KK / 4; jj++) {
                float4 al = a4[jj];
                sum = fmaf(al.x, Acol[4*jj+0], sum);
                sum = fmaf(al.y, Acol[4*jj+1], sum);
                sum = fmaf(al.z, Acol[4*jj+2], sum);
                sum = fmaf(al.w, Acol[4*jj+3], sum);
            }
            acc = p * sum;
        }

        // Block reduce over 64 threads (2 warps)
        float v = acc;
        #pragma unroll
        for (int off = 16; off; off >>= 1)
            v += __shfl_xor_sync(0xffffffffu, v, off);
        if ((k & 31) == 0) red_sh[k >> 5] = v;
        __syncthreads();                       // sync A: partials + all alpha reads done
        float dsum = red_sh[0] + red_sh[1];
        an = acc / dsum;
        alpha_sh[k] = an;                      // safe: all alpha reads happened pre-sync A
        if (k == 0) logden += __logf(dsum);
        __syncthreads();                       // sync B: alpha ready for next step
    }

    out[(size_t)s * KK + k] = an;
    if (k == 0) g_logden[s] = logden;
}

// ---------------------------------------------------------------------------
// Deterministic reduction of per-sequence log-denominators -> -log_likelihood
// (since alpha is normalized each step, logsumexp(log a + logden) = logden)
// ---------------------------------------------------------------------------
__global__ void finalize_kernel(float* __restrict__ out, int out_size) {
    __shared__ float sh[SS];
    int tid = threadIdx.x;
    sh[tid] = g_logden[tid];
    __syncthreads();
    #pragma unroll
    for (int off = SS / 2; off > 0; off >>= 1) {
        if (tid < off) sh[tid] += sh[tid + off];
        __syncthreads();
    }
    if (tid == 0 && out_size > SS * KK) {
        out[out_size - 1] = -sh[0];
    }
}

extern "C" void kernel_launch(void* const* d_in, const int* in_sizes, int n_in,
                              void* d_out, int out_size) {
    const float* data  = (const float*)d_in[0];  // [T,S,D]
    const float* initp = (const float*)d_in[1];  // [K]
    const float* A     = (const float*)d_in[2];  // [K,K]
    const float* means = (const float*)d_in[3];  // [K,D]
    const float* covar = (const float*)d_in[4];  // [K,D]
    float* out = (float*)d_out;

    precompute_kernel<<<1, KK>>>(means, covar);
    hmm_forward_kernel<<<SS, KK>>>(data, initp, A, out);
    finalize_kernel<<<1, SS>>>(out, out_size);
}

// round 6
// speedup vs baseline: 1.4998x; 1.4998x over previous
#include <cuda_runtime.h>
#include <cuda_bf16.h>
#include <math.h>

// Problem constants (fixed by the dataset)
#define TT 1024
#define SS 512
#define DD 32
#define KK 64
#define LOG2PI 1.8378770664093453f

// Precomputed per-state parameters (device globals: no allocations allowed)
__device__ float g_ninv[KK * DD];   // -0.5 / covar
__device__ float g_miv [KK * DD];   // mean / covar
__device__ float g_base[KK];        // -0.5*(sum m^2/c + sum log c + D*log(2pi))
__device__ float g_logden[SS];      // per-sequence sum of log(denominator)

// ---------------------------------------------------------------------------
// Precompute kernel: one thread per state k
// ---------------------------------------------------------------------------
__global__ void precompute_kernel(const float* __restrict__ means,
                                  const float* __restrict__ covars) {
    int k = threadIdx.x;
    if (k >= KK) return;
    float sum_m2ic = 0.0f;
    float sum_logc = 0.0f;
    #pragma unroll
    for (int d = 0; d < DD; d++) {
        float c = covars[k * DD + d];
        float m = means [k * DD + d];
        float ic = 1.0f / c;
        g_ninv[k * DD + d] = -0.5f * ic;
        g_miv [k * DD + d] = m * ic;
        sum_m2ic += m * m * ic;
        sum_logc += logf(c);
    }
    g_base[k] = -0.5f * (sum_m2ic + sum_logc + (float)DD * LOG2PI);
}

// ---------------------------------------------------------------------------
// Forward kernel: one block per sequence s, one thread per state k.
//
// Per step (ONE __syncthreads):
//   - alpha kept UNNORMALIZED (by exactly one step's denominator) in shared,
//     double-buffered; its sum (dsum) is produced by a warp-shuffle tree
//     started in the PREVIOUS step, hiding the shuffle latency.
//   - transition dot + emission both use 4 independent accumulators (ILP).
//   - CRITICAL ORDERING: acc = p * (dot * rcp(dsum_prev)). dot*r is O(1);
//     (p*dot) would underflow fp32 (both factors ~1e-20s scale).
// ---------------------------------------------------------------------------
__global__ __launch_bounds__(KK) void hmm_forward_kernel(
    const float* __restrict__ data,      // [T, S, D]
    const float* __restrict__ initp,     // [K]
    const float* __restrict__ A,         // [K, K] row-stochastic
    float* __restrict__ out)             // [S, K] alpha
{
    const int s = blockIdx.x;
    const int k = threadIdx.x;

    __shared__ __align__(16) float acc_sh[2][KK];   // unnormalized alpha, dbl-buf
    __shared__ __align__(16) float xsh[2][DD];      // x_t ring
    __shared__ float red_sh[2][2];                  // warp partial sums, dbl-buf

    // Per-state parameters into registers (float4 loads, conflict-free)
    float ninv[DD], miv[DD];
    {
        const float4* n4 = reinterpret_cast<const float4*>(&g_ninv[k * DD]);
        const float4* m4 = reinterpret_cast<const float4*>(&g_miv [k * DD]);
        #pragma unroll
        for (int i = 0; i < DD / 4; i++) {
            float4 a = n4[i];
            ninv[4*i+0] = a.x; ninv[4*i+1] = a.y; ninv[4*i+2] = a.z; ninv[4*i+3] = a.w;
            float4 b = m4[i];
            miv [4*i+0] = b.x; miv [4*i+1] = b.y; miv [4*i+2] = b.z; miv [4*i+3] = b.w;
        }
    }
    const float base  = g_base[k];
    const float initk = __ldg(&initp[k]);

    // A column for state k into registers: A[j][k]. For fixed j, lanes read
    // consecutive addresses -> fully coalesced.
    float Acol[KK];
    #pragma unroll
    for (int j = 0; j < KK; j++) Acol[j] = __ldg(&A[j * KK + k]);

    // Prologue: stage x0, x1 into shared; x2 into register
    const float* dptr = data + (size_t)s * DD;   // data[t,s,d] = data[(t*S+s)*D + d]
    float xnext = 0.0f;
    if (k < DD) {
        xsh[0][k] = __ldg(dptr + k);
        xsh[1][k] = __ldg(dptr + (size_t)1 * SS * DD + k);
        xnext     = __ldg(dptr + (size_t)2 * SS * DD + k);
    }
    float logden = 0.0f;
    __syncthreads();

    // ---- t = 0 ----
    float acc;
    {
        float e0 = 0.f, e1 = 0.f, e2 = 0.f, e3 = 0.f;
        const float4* xr4 = reinterpret_cast<const float4*>(xsh[0]);
        #pragma unroll
        for (int dd = 0; dd < DD / 4; dd++) {
            float4 x4 = xr4[dd];
            e0 = fmaf(x4.x, fmaf(ninv[4*dd+0], x4.x, miv[4*dd+0]), e0);
            e1 = fmaf(x4.y, fmaf(ninv[4*dd+1], x4.y, miv[4*dd+1]), e1);
            e2 = fmaf(x4.z, fmaf(ninv[4*dd+2], x4.z, miv[4*dd+2]), e2);
            e3 = fmaf(x4.w, fmaf(ninv[4*dd+3], x4.w, miv[4*dd+3]), e3);
        }
        float logp = base + ((e0 + e1) + (e2 + e3));
        acc = initk * __expf(logp);
        acc_sh[0][k] = acc;
        // start reduction of dsum_0 (consumed next step)
        float v = acc;
        #pragma unroll
        for (int off = 16; off; off >>= 1)
            v += __shfl_xor_sync(0xffffffffu, v, off);
        if ((k & 31) == 0) red_sh[0][k >> 5] = v;
    }
    __syncthreads();

    // ---- t = 1 .. TT-1 ----
    for (int t = 1; t < TT; t++) {
        const int cb = t & 1;       // current buffer
        const int pb = cb ^ 1;      // previous buffer

        // Stage x_{t+1}; issue load for x_{t+2} (2-deep latency hiding).
        if (k < DD) {
            if (t + 1 < TT) xsh[pb][k] = xnext;
            if (t + 2 < TT)
                xnext = __ldg(dptr + (size_t)(t + 2) * SS * DD + k);
        }

        // dsum_{t-1}: shuffle tree finished last step; just combine partials.
        float dsum = red_sh[pb][0] + red_sh[pb][1];
        float r = __frcp_rn(dsum);
        if (k == 0) logden += __logf(dsum);

        // Transition dot over unnormalized acc_{t-1} (broadcast LDS.128, 4 accs)
        float s0 = 0.f, s1 = 0.f, s2 = 0.f, s3 = 0.f;
        const float4* a4 = reinterpret_cast<const float4*>(acc_sh[pb]);
        #pragma unroll
        for (int jj = 0; jj < KK / 4; jj++) {
            float4 al = a4[jj];
            s0 = fmaf(al.x, Acol[4*jj+0], s0);
            s1 = fmaf(al.y, Acol[4*jj+1], s1);
            s2 = fmaf(al.z, Acol[4*jj+2], s2);
            s3 = fmaf(al.w, Acol[4*jj+3], s3);
        }
        float dot = (s0 + s1) + (s2 + s3);
        // Rescale to O(1) BEFORE touching p (underflow-safe ordering)
        float dotn = dot * r;

        // Emission (independent of alpha chain -> overlaps)
        float e0 = 0.f, e1 = 0.f, e2 = 0.f, e3 = 0.f;
        const float4* xr4 = reinterpret_cast<const float4*>(xsh[cb]);
        #pragma unroll
        for (int dd = 0; dd < DD / 4; dd++) {
            float4 x4 = xr4[dd];
            e0 = fmaf(x4.x, fmaf(ninv[4*dd+0], x4.x, miv[4*dd+0]), e0);
            e1 = fmaf(x4.y, fmaf(ninv[4*dd+1], x4.y, miv[4*dd+1]), e1);
            e2 = fmaf(x4.z, fmaf(ninv[4*dd+2], x4.z, miv[4*dd+2]), e2);
            e3 = fmaf(x4.w, fmaf(ninv[4*dd+3], x4.w, miv[4*dd+3]), e3);
        }
        float logp = base + ((e0 + e1) + (e2 + e3));
        float p = __expf(logp);

        acc = p * dotn;              // scale ~ p: inside fp32 range
        acc_sh[cb][k] = acc;

        // Start reduction of dsum_t (consumed next step)
        float v = acc;
        #pragma unroll
        for (int off = 16; off; off >>= 1)
            v += __shfl_xor_sync(0xffffffffu, v, off);
        if ((k & 31) == 0) red_sh[cb][k >> 5] = v;

        __syncthreads();
    }

    // Epilogue: final normalization of acc_{TT-1}
    {
        float dsum = red_sh[(TT - 1) & 1][0] + red_sh[(TT - 1) & 1][1];
        float r = __frcp_rn(dsum);
        out[(size_t)s * KK + k] = acc * r;
        if (k == 0) {
            logden += __logf(dsum);
            g_logden[s] = logden;
        }
    }
}

// ---------------------------------------------------------------------------
// Deterministic reduction of per-sequence log-denominators -> -log_likelihood
// (since alpha is normalized each step, logsumexp(log a + logden) = logden)
// ---------------------------------------------------------------------------
__global__ void finalize_kernel(float* __restrict__ out, int out_size) {
    __shared__ float sh[SS];
    int tid = threadIdx.x;
    sh[tid] = g_logden[tid];
    __syncthreads();
    #pragma unroll
    for (int off = SS / 2; off > 0; off >>= 1) {
        if (tid < off) sh[tid] += sh[tid + off];
        __syncthreads();
    }
    if (tid == 0 && out_size > SS * KK) {
        out[out_size - 1] = -sh[0];
    }
}

extern "C" void kernel_launch(void* const* d_in, const int* in_sizes, int n_in,
                              void* d_out, int out_size) {
    const float* data  = (const float*)d_in[0];  // [T,S,D]
    const float* initp = (const float*)d_in[1];  // [K]
    const float* A     = (const float*)d_in[2];  // [K,K]
    const float* means = (const float*)d_in[3];  // [K,D]
    const float* covar = (const float*)d_in[4];  // [K,D]
    float* out = (float*)d_out;

    precompute_kernel<<<1, KK>>>(means, covar);
    hmm_forward_kernel<<<SS, KK>>>(data, initp, A, out);
    finalize_kernel<<<1, SS>>>(out, out_size);
}